// round 8
// baseline (speedup 1.0000x reference)
#include <cuda_runtime.h>

#define B_   32
#define C_   256
#define HW_  4096
#define BC_  8192
#define HID_ 64
#define KSZ_ 5

#define GRID_P   1024        // persistent CTAs (all co-resident at 8/SM)
#define NCHUNK   4
#define RPC_     2048        // rows per chunk (8 batches * 256 channels)

// Scratch (__device__ globals; zero-init at load)
__device__ float g_mean[BC_];
__device__ float g_s2[BC_];
__device__ unsigned g_bar_cnt = 0;
__device__ volatile unsigned g_bar_gen = 0;

__device__ __forceinline__ float sigm(float v) {
    return 1.0f / (1.0f + __expf(-v));
}
__device__ __forceinline__ float tanh_fast(float v) {
    float r;
    asm("tanh.approx.f32 %0, %1;" : "=f"(r) : "f"(v));
    return r;
}

// Software grid barrier (all GRID_P CTAs co-resident by construction).
__device__ __forceinline__ void grid_sync() {
    __syncthreads();
    if (threadIdx.x == 0) {
        __threadfence();
        const unsigned gen = g_bar_gen;
        if (atomicAdd(&g_bar_cnt, 1u) == GRID_P - 1) {
            g_bar_cnt = 0;
            __threadfence();
            g_bar_gen = gen + 1;
        } else {
            while (g_bar_gen == gen) { __nanosleep(64); }
        }
        __threadfence();
    }
    __syncthreads();
}

// ---------------------------------------------------------------------------
// Persistent fused kernel: per chunk of 8 batches (32 MB of x):
//   phase A: stats for this CTA's 2 rows (DRAM read, fills L2)
//   grid barrier
//   phase B: redundant per-CTA batch gate (L2-hit stat loads) + out for the
//            same 2 rows (x re-read = L2 hit; streaming stores)
// ---------------------------------------------------------------------------
__global__ void __launch_bounds__(256, 8) fused_kernel(const float* __restrict__ x,
                                                       const float* __restrict__ cw,
                                                       const float* __restrict__ w1,
                                                       const float* __restrict__ w2,
                                                       float* __restrict__ out)
{
    const int t   = threadIdx.x;
    const int bid = blockIdx.x;
    const int w   = t >> 5, l = t & 31;

    __shared__ float shS[8], shQ[8], bcast[2];
    __shared__ float m[C_], gap[C_], gate_s[C_], alpha_s[C_], hid[HID_];

    float meanR[2], h4vR[2];

    for (int ch = 0; ch < NCHUNK; ch++) {
        const int base = ch * RPC_ + bid * 2;          // first of this CTA's 2 rows

        // ---------------- phase A: stats for rows base, base+1 ----------------
#pragma unroll
        for (int r = 0; r < 2; r++) {
            const int row = base + r;
            const float4* xr = (const float4*)(x + (size_t)row * HW_);

            float4 v[4];
#pragma unroll
            for (int j = 0; j < 4; j++) v[j] = xr[t + j * 256];

            float s = 0.f, ss = 0.f;
#pragma unroll
            for (int j = 0; j < 4; j++) {
                float4 q = v[j];
                s  += (q.x + q.y) + (q.z + q.w);
                ss += q.x * q.x + q.y * q.y + q.z * q.z + q.w * q.w;
            }
#pragma unroll
            for (int o = 16; o > 0; o >>= 1) {
                s  += __shfl_xor_sync(0xffffffffu, s,  o);
                ss += __shfl_xor_sync(0xffffffffu, ss, o);
            }
            if (l == 0) { shS[w] = s; shQ[w] = ss; }
            __syncthreads();
            if (t == 0) {
                float S = 0.f, Q = 0.f;
#pragma unroll
                for (int i = 0; i < 8; i++) { S += shS[i]; Q += shQ[i]; }
                const float mean = S * (1.0f / HW_);
                const float var  = (Q - (float)HW_ * mean * mean) * (1.0f / (HW_ - 1));
                const float h4v  = 0.125f / (var + 1e-4f);
                bcast[0] = mean; bcast[1] = h4v;
                g_mean[row] = mean;
            }
            __syncthreads();
            const float mean = bcast[0];
            const float h4v  = bcast[1];
            meanR[r] = mean; h4vR[r] = h4v;

            float s2 = 0.f;
#pragma unroll
            for (int j = 0; j < 4; j++) {
                float4 q = v[j];
                float d, th;
                d = q.x - mean; th = tanh_fast(fmaf(d * d, h4v, 0.25f)); s2 = fmaf(q.x, fmaf(th, 0.5f, 0.5f), s2);
                d = q.y - mean; th = tanh_fast(fmaf(d * d, h4v, 0.25f)); s2 = fmaf(q.y, fmaf(th, 0.5f, 0.5f), s2);
                d = q.z - mean; th = tanh_fast(fmaf(d * d, h4v, 0.25f)); s2 = fmaf(q.z, fmaf(th, 0.5f, 0.5f), s2);
                d = q.w - mean; th = tanh_fast(fmaf(d * d, h4v, 0.25f)); s2 = fmaf(q.w, fmaf(th, 0.5f, 0.5f), s2);
            }
#pragma unroll
            for (int o = 16; o > 0; o >>= 1)
                s2 += __shfl_xor_sync(0xffffffffu, s2, o);
            if (l == 0) shS[w] = s2;
            __syncthreads();
            if (t == 0) {
                float S = 0.f;
#pragma unroll
                for (int i = 0; i < 8; i++) S += shS[i];
                g_s2[row] = S;
            }
            __syncthreads();
        }

        grid_sync();                                   // all stats of chunk visible

        // ---------------- phase B1: per-CTA batch gate (redundant) ------------
        const int batch = base >> 8;                   // global batch of both rows
        const int c = t;
        m[c]            = __ldcg(&g_mean[batch * C_ + c]);
        const float s2c = __ldcg(&g_s2[batch * C_ + c]);
        __syncthreads();

        float y = 0.f;
#pragma unroll
        for (int k = 0; k < KSZ_; k++) {
            const int cc = c + k - (KSZ_ - 1) / 2;
            const float mv = (cc >= 0 && cc < C_) ? m[cc] : 0.f;
            y = fmaf(mv, cw[k], y);
        }
        const float gate = sigm(y);
        gate_s[c] = gate;
        gap[c] = fmaf(gate, m[c], s2c * (1.0f / HW_));
        __syncthreads();

        {   // hid[j] = relu(sum_c gap[c]*w1[j,c]); 4 threads per j
            const int j = c >> 2, p = c & 3;
            float h = 0.f;
            const float* w1r = w1 + j * C_ + p * 64;
            const float* gp  = gap + p * 64;
#pragma unroll 8
            for (int i = 0; i < 64; i++) h = fmaf(gp[i], w1r[i], h);
            h += __shfl_xor_sync(0xffffffffu, h, 1);
            h += __shfl_xor_sync(0xffffffffu, h, 2);
            if (p == 0) hid[j] = fmaxf(h, 0.f);
        }
        __syncthreads();

        {
            float a = 0.f;
            const float* w2r = w2 + c * HID_;
#pragma unroll 8
            for (int j = 0; j < HID_; j++) a = fmaf(hid[j], w2r[j], a);
            alpha_s[c] = sigm(a);
        }
        __syncthreads();

        // ---------------- phase B2: out for rows base, base+1 (L2 hits) -------
#pragma unroll
        for (int r = 0; r < 2; r++) {
            const int row  = base + r;
            const int crow = row & (C_ - 1);
            const float mean  = meanR[r];
            const float h4v   = h4vR[r];
            const float alpha = alpha_s[crow];
            const float a2    = 0.5f * alpha;
            const float a3    = fmaf(1.0f - alpha, gate_s[crow], a2);

            const float4* xr = (const float4*)(x   + (size_t)row * HW_);
            float4*       ow = (float4*)     (out + (size_t)row * HW_);

            float4 q[4];
#pragma unroll
            for (int j = 0; j < 4; j++) q[j] = xr[t + j * 256];
#pragma unroll
            for (int j = 0; j < 4; j++) {
                float d, th;
                d = q[j].x - mean; th = tanh_fast(fmaf(d * d, h4v, 0.25f)); q[j].x = q[j].x * fmaf(a2, th, a3);
                d = q[j].y - mean; th = tanh_fast(fmaf(d * d, h4v, 0.25f)); q[j].y = q[j].y * fmaf(a2, th, a3);
                d = q[j].z - mean; th = tanh_fast(fmaf(d * d, h4v, 0.25f)); q[j].z = q[j].z * fmaf(a2, th, a3);
                d = q[j].w - mean; th = tanh_fast(fmaf(d * d, h4v, 0.25f)); q[j].w = q[j].w * fmaf(a2, th, a3);
            }
#pragma unroll
            for (int j = 0; j < 4; j++) __stcs(&ow[t + j * 256], q[j]);
        }
        __syncthreads();   // protect smem reuse next chunk
    }
}

// ---------------------------------------------------------------------------
extern "C" void kernel_launch(void* const* d_in, const int* in_sizes, int n_in,
                              void* d_out, int out_size)
{
    const float* x  = (const float*)d_in[0];   // [B, C, H, W]
    const float* cw = (const float*)d_in[1];   // [1, 1, 5]
    const float* w1 = (const float*)d_in[2];   // [HID, C]
    const float* w2 = (const float*)d_in[3];   // [C, HID]
    float* out = (float*)d_out;

    fused_kernel<<<GRID_P, 256>>>(x, cw, w1, w2, out);
}

// round 10
// speedup vs baseline: 7.4790x; 7.4790x over previous
#include <cuda_runtime.h>

#define B_   32
#define C_   256
#define H_   64
#define W_   64
#define HW_  4096            // H*W
#define BC_  8192            // B*C
#define HID_ 64
#define KSZ_ 5

// Scratch (allocation-free rule: __device__ globals)
__device__ float g_mean[BC_];
__device__ float g_h4v[BC_];    // 0.125 / (var + 1e-4)
__device__ float g_s2[BC_];     // sum over HW of x*sigmoid(energy)
__device__ float g_gate[BC_];   // ECA gate
__device__ float g_alpha[BC_];  // fusion gate

__device__ __forceinline__ float sigm(float v) {          // tiny gate math only
    return 1.0f / (1.0f + __expf(-v));
}
__device__ __forceinline__ float tanh_fast(float v) {     // MUFU.TANH, 1 MUFU
    float r;
    asm("tanh.approx.f32 %0, %1;" : "=f"(r) : "f"(v));
    return r;
}

struct F8 { float4 a, b; };    // 32-byte vector

// 32-byte load pinned into L2 with lowest eviction priority (sm_103a needs v4.b64)
__device__ __forceinline__ F8 ldg32_evict_last(const void* p) {
    unsigned long long r0, r1, r2, r3;
    asm volatile("ld.global.L2::evict_last.v4.b64 {%0,%1,%2,%3}, [%4];"
                 : "=l"(r0), "=l"(r1), "=l"(r2), "=l"(r3) : "l"(p));
    F8 v;
    v.a.x = __uint_as_float((unsigned)(r0));
    v.a.y = __uint_as_float((unsigned)(r0 >> 32));
    v.a.z = __uint_as_float((unsigned)(r1));
    v.a.w = __uint_as_float((unsigned)(r1 >> 32));
    v.b.x = __uint_as_float((unsigned)(r2));
    v.b.y = __uint_as_float((unsigned)(r2 >> 32));
    v.b.z = __uint_as_float((unsigned)(r3));
    v.b.w = __uint_as_float((unsigned)(r3 >> 32));
    return v;
}

// ---------------------------------------------------------------------------
// Kernel 1: per-(b,c) stats + SimAM-weighted sum.
// Reads x (16 floats/thread as 2x32B) with L2::evict_last so out_kernel's
// re-read hits L2.
// ---------------------------------------------------------------------------
__global__ void __launch_bounds__(256, 8) stat_kernel(const float* __restrict__ x)
{
    const int row = blockIdx.x;                    // b*C + c
    const int t   = threadIdx.x;
    const float* xr = x + (size_t)row * HW_;

    F8 v[2];
#pragma unroll
    for (int j = 0; j < 2; j++) v[j] = ldg32_evict_last(xr + t * 8 + j * 2048);

    float s = 0.f, ss = 0.f;
#pragma unroll
    for (int j = 0; j < 2; j++) {
        float4 q = v[j].a;
        s  += (q.x + q.y) + (q.z + q.w);
        ss += q.x * q.x + q.y * q.y + q.z * q.z + q.w * q.w;
        q = v[j].b;
        s  += (q.x + q.y) + (q.z + q.w);
        ss += q.x * q.x + q.y * q.y + q.z * q.z + q.w * q.w;
    }
#pragma unroll
    for (int o = 16; o > 0; o >>= 1) {
        s  += __shfl_xor_sync(0xffffffffu, s,  o);
        ss += __shfl_xor_sync(0xffffffffu, ss, o);
    }

    __shared__ float shS[8], shQ[8], bcast[2];
    const int w = t >> 5, l = t & 31;
    if (l == 0) { shS[w] = s; shQ[w] = ss; }
    __syncthreads();
    if (t == 0) {
        float S = 0.f, Q = 0.f;
#pragma unroll
        for (int i = 0; i < 8; i++) { S += shS[i]; Q += shQ[i]; }
        const float mean = S * (1.0f / HW_);
        const float var  = (Q - (float)HW_ * mean * mean) * (1.0f / (HW_ - 1));
        const float h4v  = 0.125f / (var + 1e-4f);   // = 0.5 * 1/(4(var+eps))
        bcast[0] = mean; bcast[1] = h4v;
        g_mean[row] = mean;
        g_h4v[row]  = h4v;
    }
    __syncthreads();
    const float mean = bcast[0];
    const float h4v  = bcast[1];

    float s2 = 0.f;
#pragma unroll
    for (int j = 0; j < 2; j++) {
        float d, th;
        float4 q = v[j].a;
        d = q.x - mean; th = tanh_fast(fmaf(d * d, h4v, 0.25f)); s2 = fmaf(q.x, fmaf(th, 0.5f, 0.5f), s2);
        d = q.y - mean; th = tanh_fast(fmaf(d * d, h4v, 0.25f)); s2 = fmaf(q.y, fmaf(th, 0.5f, 0.5f), s2);
        d = q.z - mean; th = tanh_fast(fmaf(d * d, h4v, 0.25f)); s2 = fmaf(q.z, fmaf(th, 0.5f, 0.5f), s2);
        d = q.w - mean; th = tanh_fast(fmaf(d * d, h4v, 0.25f)); s2 = fmaf(q.w, fmaf(th, 0.5f, 0.5f), s2);
        q = v[j].b;
        d = q.x - mean; th = tanh_fast(fmaf(d * d, h4v, 0.25f)); s2 = fmaf(q.x, fmaf(th, 0.5f, 0.5f), s2);
        d = q.y - mean; th = tanh_fast(fmaf(d * d, h4v, 0.25f)); s2 = fmaf(q.y, fmaf(th, 0.5f, 0.5f), s2);
        d = q.z - mean; th = tanh_fast(fmaf(d * d, h4v, 0.25f)); s2 = fmaf(q.z, fmaf(th, 0.5f, 0.5f), s2);
        d = q.w - mean; th = tanh_fast(fmaf(d * d, h4v, 0.25f)); s2 = fmaf(q.w, fmaf(th, 0.5f, 0.5f), s2);
    }
#pragma unroll
    for (int o = 16; o > 0; o >>= 1)
        s2 += __shfl_xor_sync(0xffffffffu, s2, o);
    if (l == 0) shS[w] = s2;
    __syncthreads();
    if (t == 0) {
        float S = 0.f;
#pragma unroll
        for (int i = 0; i < 8; i++) S += shS[i];
        g_s2[row] = S;
    }
}

// ---------------------------------------------------------------------------
// Kernel 2: per-batch ECA conv + fusion MLP (tiny). One CTA per batch.
// ---------------------------------------------------------------------------
__global__ void __launch_bounds__(256) gate_kernel(const float* __restrict__ cw,
                                                   const float* __restrict__ w1,
                                                   const float* __restrict__ w2)
{
    const int b = blockIdx.x;
    const int c = threadIdx.x;        // 0..255
    const int idx = b * C_ + c;

    __shared__ float m[C_], gap[C_], hid[HID_];
    m[c] = g_mean[idx];
    __syncthreads();

    // ECA: cross-correlation over channel dim, zero-padded, K=5
    float y = 0.f;
#pragma unroll
    for (int k = 0; k < KSZ_; k++) {
        const int cc = c + k - (KSZ_ - 1) / 2;
        const float mv = (cc >= 0 && cc < C_) ? m[cc] : 0.f;
        y = fmaf(mv, cw[k], y);
    }
    const float gate = sigm(y);
    g_gate[idx] = gate;
    gap[c] = fmaf(gate, m[c], g_s2[idx] * (1.0f / HW_));
    __syncthreads();

    // hid[j] = relu(sum_c gap[c] * w1[j, c]); 4 threads per output j
    {
        const int j = c >> 2;          // 0..63
        const int p = c & 3;           // 0..3
        float h = 0.f;
        const float* w1r = w1 + j * C_ + p * 64;
        const float* gp  = gap + p * 64;
#pragma unroll 8
        for (int i = 0; i < 64; i++) h = fmaf(gp[i], w1r[i], h);
        h += __shfl_xor_sync(0xffffffffu, h, 1);
        h += __shfl_xor_sync(0xffffffffu, h, 2);
        if (p == 0) hid[j] = fmaxf(h, 0.f);
    }
    __syncthreads();

    // alpha[c] = sigmoid(sum_j hid[j] * w2[c, j]), w2 is [C, HID] row-major
    float a = 0.f;
    const float* w2r = w2 + c * HID_;
#pragma unroll 8
    for (int j = 0; j < HID_; j++) a = fmaf(hid[j], w2r[j], a);
    g_alpha[idx] = sigm(a);
}

// ---------------------------------------------------------------------------
// Kernel 3: out = x * (alpha*sigmoid(energy) + (1-alpha)*gate)
// x re-read should now hit L2 (evict_last pin from stat_kernel).
// Reverse row order still targets the freshest tail first.
// Streaming (evict_first) stores keep writes from evicting pinned x.
// ---------------------------------------------------------------------------
__global__ void __launch_bounds__(256, 8) out_kernel(const float* __restrict__ x,
                                                     float* __restrict__ out)
{
    const int row = BC_ - 1 - blockIdx.x;
    const int t   = threadIdx.x;

    const float mean  = g_mean[row];
    const float h4v   = g_h4v[row];
    const float alpha = g_alpha[row];
    const float a2    = 0.5f * alpha;
    const float a3    = fmaf(1.0f - alpha, g_gate[row], a2);

    const float4* xr = (const float4*)(x   + (size_t)row * HW_);
    float4*       ow = (float4*)     (out + (size_t)row * HW_);

    float4 q[4];
#pragma unroll
    for (int j = 0; j < 4; j++) q[j] = xr[t + j * 256];

#pragma unroll
    for (int j = 0; j < 4; j++) {
        float d, th;
        d = q[j].x - mean; th = tanh_fast(fmaf(d * d, h4v, 0.25f)); q[j].x = q[j].x * fmaf(a2, th, a3);
        d = q[j].y - mean; th = tanh_fast(fmaf(d * d, h4v, 0.25f)); q[j].y = q[j].y * fmaf(a2, th, a3);
        d = q[j].z - mean; th = tanh_fast(fmaf(d * d, h4v, 0.25f)); q[j].z = q[j].z * fmaf(a2, th, a3);
        d = q[j].w - mean; th = tanh_fast(fmaf(d * d, h4v, 0.25f)); q[j].w = q[j].w * fmaf(a2, th, a3);
    }

#pragma unroll
    for (int j = 0; j < 4; j++) __stcs(&ow[t + j * 256], q[j]);
}

// ---------------------------------------------------------------------------
extern "C" void kernel_launch(void* const* d_in, const int* in_sizes, int n_in,
                              void* d_out, int out_size)
{
    const float* x  = (const float*)d_in[0];   // [B, C, H, W]
    const float* cw = (const float*)d_in[1];   // [1, 1, 5]
    const float* w1 = (const float*)d_in[2];   // [HID, C]
    const float* w2 = (const float*)d_in[3];   // [C, HID]
    float* out = (float*)d_out;

    stat_kernel<<<BC_, 256>>>(x);
    gate_kernel<<<B_, 256>>>(cw, w1, w2);
    out_kernel<<<BC_, 256>>>(x, out);
}